// round 7
// baseline (speedup 1.0000x reference)
#include <cuda_runtime.h>
#include <cstdint>

#define FULLM 0xFFFFFFFFu
#define NEGF (-1e30f)
#define LOG2E 1.4426950408889634f
#define LN2F 0.6931471805599453f
#define CC 37
#define BLANKC 36
#define WARPS_PER_BLK 4

// Per-sample loss scratch (no device allocation allowed -> static __device__)
__device__ float g_loss[8192];

__device__ __forceinline__ float ex2f_(float x) {
    float y; asm("ex2.approx.f32 %0, %1;" : "=f"(y) : "f"(x)); return y;
}
__device__ __forceinline__ float lg2f_(float x) {
    float y; asm("lg2.approx.f32 %0, %1;" : "=f"(y) : "f"(x)); return y;
}

extern __shared__ float smem_dyn[];

// One warp per batch sample. Lane k owns CTC state k+1; state 0 is replicated
// in all lanes (pure accumulator, no logaddexp). All log math in base-2 so
// logaddexp = max + ex2 + lg2 (pure MUFU, no scale multiplies in the loop).
__global__ void __launch_bounds__(WARPS_PER_BLK * 32, 3)
ctc_kernel(const float* __restrict__ logits,
           const int*   __restrict__ targets,
           const int*   __restrict__ in_len,
           const int*   __restrict__ tgt_len,
           int B, int T, int L)
{
    const int warp = threadIdx.x >> 5;
    const int lane = threadIdx.x & 31;
    const int b = blockIdx.x * WARPS_PER_BLK + warp;
    if (b >= B) return;

    const int strideL = T + 1;                 // odd stride -> conflict-free smem
    const int perWarpFloats = T + L * strideL + L;
    float* lpb = smem_dyn + warp * perWarpFloats;   // [T]        log2 p(blank | t)
    float* lpl = lpb + T;                           // [L][T+1]   log2 p(tgt[l] | t)
    int*   tg  = (int*)(lpl + L * strideL);         // [L]        target labels

    for (int l = lane; l < L; l += 32) tg[l] = targets[b * L + l];
    __syncwarp();

    // ---------------- Phase A: log-softmax (base 2), gather needed classes ----
    const float* baseRow = logits + (size_t)b * T * CC;
    for (int t = lane; t < T; t += 32) {
        const float* row = baseRow + (size_t)t * CC;
        float x[CC];
        #pragma unroll
        for (int c = 0; c < CC; c++) x[c] = __ldg(row + c);
        float m = x[0];
        #pragma unroll
        for (int c = 1; c < CC; c++) m = fmaxf(m, x[c]);
        float s = 0.f;
        #pragma unroll
        for (int c = 0; c < CC; c++) s += ex2f_((x[c] - m) * LOG2E);
        const float Z2 = m * LOG2E + lg2f_(s);      // log2(sum exp(x))
        lpb[t] = x[BLANKC] * LOG2E - Z2;
        for (int l = 0; l < L; l++) {
            // dynamic class index: reload from global (L1-hot), regs stay static
            lpl[l * strideL + t] = __ldg(row + tg[l]) * LOG2E - Z2;
        }
    }
    __syncwarp();

    // ---------------- Phase B: forward recursion --------------------------
    const int tl   = tgt_len[b];
    const int il   = in_len[b];
    const int endi = 2 * tl;        // end state index
    const int S    = endi + 1;

    const int  s     = lane + 1;            // my state (1..32)
    const bool sOdd  = (s & 1);             // odd state = label, even = blank
    const int  li    = (s - 1) >> 1;        // label index for odd states
    const bool canSkip = sOdd && (s >= 3) && (tg[li] != tg[li - 1]);
    const bool vS    = (s < S);
    const float* myLpl = lpl + li * strideL;

    // t = 0 init
    float lpbt = lpb[0];
    float a0    = lpbt;                         // state 0 (always valid)
    float alpha = (s == 1) ? myLpl[0] : NEGF;   // state 1 = first label
    alpha = vS ? alpha : NEGF;
    float fin = NEGF;

#define CTC_CAPTURE() do {                                                   \
        float e1 = (endi == 0) ? a0 : __shfl_sync(FULLM, alpha, endi - 1);   \
        float e2 = (endi == 1) ? a0 :                                        \
                   ((endi >= 2) ? __shfl_sync(FULLM, alpha, endi - 2) : NEGF); \
        float mm = fmaxf(e1, e2);                                            \
        fin = mm + lg2f_(ex2f_(e1 - mm) + ex2f_(e2 - mm));                   \
    } while (0)

    if (il == 1) CTC_CAPTURE();

    for (int t = 1; t < T; t++) {
        lpbt = lpb[t];
        float a1 = __shfl_up_sync(FULLM, alpha, 1);
        if (lane == 0) a1 = a0;                  // state 1's predecessor = state 0
        float a2 = __shfl_up_sync(FULLM, alpha, 2);
        a2 = canSkip ? a2 : NEGF;                // skip path only for distinct labels
        const float lp = sOdd ? myLpl[t] : lpbt;

        float m   = fmaxf(fmaxf(alpha, a1), a2);
        float sum = ex2f_(alpha - m) + ex2f_(a1 - m) + ex2f_(a2 - m);
        float na  = m + lg2f_(sum) + lp;
        alpha = vS ? na : NEGF;
        a0 += lpbt;                              // state 0: blank self-loop only

        if (t + 1 == il) CTC_CAPTURE();          // uniform branch per warp
    }
#undef CTC_CAPTURE

    if (lane == 0) {
        float tlf = (float)(tl > 0 ? tl : 1);
        g_loss[b] = -(fin * LN2F) / tlf;
    }
}

// Deterministic fixed-order mean reduction (no float atomics -> replay-stable)
__global__ void ctc_reduce_kernel(float* __restrict__ out, int B)
{
    __shared__ float sh[256];
    const int tid = threadIdx.x;
    float s = 0.f;
    for (int i = tid; i < B; i += 256) s += g_loss[i];
    sh[tid] = s;
    __syncthreads();
    #pragma unroll
    for (int k = 128; k > 0; k >>= 1) {
        if (tid < k) sh[tid] += sh[tid + k];
        __syncthreads();
    }
    if (tid == 0) out[0] = sh[0] / (float)B;
}

extern "C" void kernel_launch(void* const* d_in, const int* in_sizes, int n_in,
                              void* d_out, int out_size)
{
    const float* logits  = (const float*)d_in[0];
    const int*   targets = (const int*)d_in[1];
    const int*   in_len  = (const int*)d_in[2];
    const int*   tgt_len = (const int*)d_in[3];

    const int B = in_sizes[2];
    const int L = in_sizes[1] / B;
    const int T = in_sizes[0] / (B * CC);

    const int perWarpFloats = T + L * (T + 1) + L;
    const size_t smemBytes = (size_t)WARPS_PER_BLK * perWarpFloats * sizeof(float);

    // Idempotent, capture-safe (not a stream op); needed for >48KB dynamic smem
    cudaFuncSetAttribute(ctc_kernel, cudaFuncAttributeMaxDynamicSharedMemorySize,
                         (int)smemBytes);

    const int blocks = (B + WARPS_PER_BLK - 1) / WARPS_PER_BLK;
    ctc_kernel<<<blocks, WARPS_PER_BLK * 32, smemBytes>>>(
        logits, targets, in_len, tgt_len, B, T, L);
    ctc_reduce_kernel<<<1, 256>>>((float*)d_out, B);
}

// round 11
// speedup vs baseline: 3.1553x; 3.1553x over previous
#include <cuda_runtime.h>
#include <cstdint>

#define FULLM 0xFFFFFFFFu
#define LOG2E 1.4426950408889634f
#define LN2F  0.6931471805599453f
#define CC 37
#define BLANKC 36
#define WPB 2
#define TILE 32
#define RENORM_K 4
#define PER_WARP (TILE*CC + TILE*17 + 20)   // tile buf + prob buf + targets pad

// Static device scratch (no allocation allowed)
__device__ float    g_loss[8192];
__device__ unsigned g_ctr = 0;

__device__ __forceinline__ float ex2f_(float x){float y;asm("ex2.approx.f32 %0,%1;":"=f"(y):"f"(x));return y;}
__device__ __forceinline__ float lg2f_(float x){float y;asm("lg2.approx.f32 %0,%1;":"=f"(y):"f"(x));return y;}
__device__ __forceinline__ float rcpf_(float x){float y;asm("rcp.approx.f32 %0,%1;":"=f"(y):"f"(x));return y;}

extern __shared__ float smem_dyn[];

// One warp per sample. Lane k owns CTC state k+1 (states 1..32); state 0 is a
// replicated pure-blank accumulator (no shuffle needed for it). Forward
// recursion runs in LINEAR probability domain (zero MUFU in the T-loop);
// exact power-of-2 renorm every RENORM_K steps keeps values in range, with
// the exponent tracked exactly in acc2 (log2 domain).
__global__ void __launch_bounds__(WPB*32)
ctc_kernel(const float* __restrict__ logits,
           const int*   __restrict__ targets,
           const int*   __restrict__ in_len,
           const int*   __restrict__ tgt_len,
           float*       __restrict__ out,
           int B, int T, int L, int nBlocks)
{
    const int warp = threadIdx.x >> 5;
    const int lane = threadIdx.x & 31;
    const int b = blockIdx.x * WPB + warp;

    float* tileB = smem_dyn + warp * PER_WARP;   // [TILE][CC]  logits*log2e tile
    float* P     = tileB + TILE*CC;              // [TILE][17]  probs: 0..15 labels, 16 blank
    int*   tg    = (int*)(P + TILE*17);          // [L] labels

    if (b < B) {
        for (int l = lane; l < L; l += 32) tg[l] = targets[b*L + l];
        __syncwarp();

        const int tl   = tgt_len[b];
        const int il   = in_len[b];
        const int endi = 2 * tl;
        const int S    = endi + 1;
        const int  s    = lane + 1;
        const bool sOdd = (s & 1);
        const int  li   = (s - 1) >> 1;
        const bool canSkip = sOdd && (s >= 3) && (tg[li] != tg[li-1]);
        const bool vS   = (s < S);
        const int  myIdx = sOdd ? li : 16;       // prob-row slot for my state

        float alpha = 0.f, a0 = 0.f, acc2 = 0.f, fin = -1e30f;
        int t = 0;

        for (int t0 = 0; t0 < T; t0 += TILE) {
            const int rows = min(TILE, T - t0);
            // ---- coalesced global->smem copy (pre-scaled to log2 domain) ----
            const float* src = logits + ((size_t)b * T + t0) * CC;
            const int nf = rows * CC;
            if (nf == TILE*CC) {                 // full tile: 1184 floats = 296 float4
                #pragma unroll 4
                for (int j = lane; j < (TILE*CC)/4; j += 32) {
                    float4 v = __ldg((const float4*)src + j);
                    v.x *= LOG2E; v.y *= LOG2E; v.z *= LOG2E; v.w *= LOG2E;
                    ((float4*)tileB)[j] = v;
                }
            } else {
                const int n4 = nf >> 2;
                for (int j = lane; j < n4; j += 32) {
                    float4 v = __ldg((const float4*)src + j);
                    v.x *= LOG2E; v.y *= LOG2E; v.z *= LOG2E; v.w *= LOG2E;
                    ((float4*)tileB)[j] = v;
                }
                for (int j = (n4 << 2) + lane; j < nf; j += 32)
                    tileB[j] = __ldg(src + j) * LOG2E;
            }
            __syncwarp();

            // ---- softmax per row (lane = row); stride 37 -> conflict-free ----
            if (lane < rows) {
                const float* xr = tileB + lane * CC;
                float m0 = xr[0], m1 = xr[1];
                #pragma unroll
                for (int c = 2; c + 1 < CC; c += 2) {
                    m0 = fmaxf(m0, xr[c]); m1 = fmaxf(m1, xr[c+1]);
                }
                const float m = fmaxf(fmaxf(m0, m1), xr[CC-1]);
                float s0 = 0.f, s1 = 0.f;
                #pragma unroll
                for (int c = 0; c + 1 < CC; c += 2) {
                    s0 += ex2f_(xr[c] - m); s1 += ex2f_(xr[c+1] - m);
                }
                s0 += ex2f_(xr[CC-1] - m);
                const float rinv = rcpf_(s0 + s1);
                float* pr = P + lane * 17;
                pr[16] = ex2f_(xr[BLANKC] - m) * rinv;
                for (int l = 0; l < L; l++)
                    pr[l] = ex2f_(xr[tg[l]] - m) * rinv;
            }
            __syncwarp();

            // ---- forward recursion over this tile ----
            int tt = 0;
            if (t0 == 0) {
                a0 = P[16];
                alpha = (s == 1 && vS) ? P[0] : 0.f;
                acc2 = 0.f;
                if (il == 1) {
                    float e1 = (endi == 0) ? a0 : __shfl_sync(FULLM, alpha, endi-1);
                    float e2 = (endi == 1) ? a0 :
                               ((endi >= 2) ? __shfl_sync(FULLM, alpha, endi-2) : 0.f);
                    fin = lg2f_(e1 + e2) + acc2;
                }
                tt = 1; t = 1;
            }
            const float* pr = P + tt * 17;
            for (; tt < rows; tt++, t++, pr += 17) {
                const float pb = pr[16];
                const float pm = pr[myIdx];
                float a1 = __shfl_up_sync(FULLM, alpha, 1);
                if (lane == 0) a1 = a0;
                float a2 = __shfl_up_sync(FULLM, alpha, 2);
                a2 = canSkip ? a2 : 0.f;
                const float na = (alpha + a1 + a2) * pm;
                alpha = vS ? na : 0.f;
                a0 *= pb;

                if ((t & (RENORM_K - 1)) == 0) {
                    // exact power-of-2 renorm; values >= 0 so float bits are monotone
                    unsigned Mi = __reduce_max_sync(FULLM,
                        (unsigned)__float_as_uint(fmaxf(alpha, a0)));
                    int e = (int)(Mi >> 23) - 127;
                    float scale = __uint_as_float((unsigned)(127 - e) << 23);
                    alpha *= scale; a0 *= scale; acc2 += (float)e;
                }
                if (t + 1 == il) {
                    float e1 = (endi == 0) ? a0 : __shfl_sync(FULLM, alpha, endi-1);
                    float e2 = (endi == 1) ? a0 :
                               ((endi >= 2) ? __shfl_sync(FULLM, alpha, endi-2) : 0.f);
                    fin = lg2f_(e1 + e2) + acc2;
                }
            }
            __syncwarp();
        }

        if (lane == 0) {
            const float tlf = (float)(tl > 0 ? tl : 1);
            g_loss[b] = -(fin * LN2F) / tlf;
        }
    }

    // ---- fused deterministic mean via last-block ticket ----
    __shared__ unsigned tkt;
    __syncthreads();
    if (threadIdx.x == 0) {
        __threadfence();
        tkt = atomicAdd(&g_ctr, 1u);
    }
    __syncthreads();
    if (tkt == (unsigned)(nBlocks - 1)) {
        __threadfence();
        float sacc = 0.f;
        for (int i = threadIdx.x; i < B; i += WPB*32) sacc += g_loss[i];
        __shared__ float sh[WPB*32];
        sh[threadIdx.x] = sacc;
        __syncthreads();
        if (threadIdx.x < 32) {
            float v = sh[threadIdx.x] + sh[threadIdx.x + 32];
            #pragma unroll
            for (int o = 16; o; o >>= 1) v += __shfl_down_sync(FULLM, v, o);
            if (threadIdx.x == 0) {
                out[0] = v / (float)B;
                g_ctr = 0;   // reset so graph replays are identical
            }
        }
    }
}

extern "C" void kernel_launch(void* const* d_in, const int* in_sizes, int n_in,
                              void* d_out, int out_size)
{
    const float* logits  = (const float*)d_in[0];
    const int*   targets = (const int*)d_in[1];
    const int*   in_len  = (const int*)d_in[2];
    const int*   tgt_len = (const int*)d_in[3];

    const int B = in_sizes[2];
    const int L = in_sizes[1] / B;
    const int T = in_sizes[0] / (B * CC);

    const int blocks = (B + WPB - 1) / WPB;
    const size_t smemBytes = (size_t)WPB * PER_WARP * sizeof(float);

    ctc_kernel<<<blocks, WPB*32, smemBytes>>>(
        logits, targets, in_len, tgt_len, (float*)d_out, B, T, L, blocks);
}